// round 8
// baseline (speedup 1.0000x reference)
#include <cuda_runtime.h>
#include <cuda.h>
#include <cuda_bf16.h>
#include <cstdint>
#include <cstddef>

#define HID 128
#define BM 128
#define TILE_BYTES 65536
#define GRID 148
#define NTHREADS 256

// ---------------- device scratch ----------------
__device__ float g_A[HID * HID];                 // Wo @ W_mo
__device__ float g_B[HID * HID];                 // Wiv @ Wv
__device__ float g_u[HID];
__device__ float g_w[HID];
__device__ __nv_bfloat16 g_Bf[16 * 8 * 2 * 32 * 2]; // 0.5*M^T bf16, mma-B-fragment layout
__device__ float g_c[HID];                       // 0.5*(A@u + w)
__device__ unsigned int g_tile_ctr;              // dynamic tile tickets (reset in prep1)

__device__ __forceinline__ uint32_t smem_u32(const void* p) {
    uint32_t a;
    asm("{ .reg .u64 t; cvta.to.shared.u64 t, %1; cvt.u32.u64 %0, t; }" : "=r"(a) : "l"(p));
    return a;
}
__device__ __forceinline__ float warp_red(float p) {
    p += __shfl_xor_sync(0xffffffffu, p, 16);
    p += __shfl_xor_sync(0xffffffffu, p, 8);
    p += __shfl_xor_sync(0xffffffffu, p, 4);
    p += __shfl_xor_sync(0xffffffffu, p, 2);
    p += __shfl_xor_sync(0xffffffffu, p, 1);
    return p;
}
#define CPA16(dst, src) \
    asm volatile("cp.async.cg.shared.global [%0], [%1], 16;" :: "r"(dst), "l"(src))
#define CPA_WAIT_ALL() \
    asm volatile("cp.async.commit_group;\ncp.async.wait_group 0;" ::: "memory")

// ================= prep1: A = Wo@W_mo, B = Wiv@Wv, u, w ===================
__global__ __launch_bounds__(256) void prep1(
    const float* __restrict__ Wo, const float* __restrict__ W_mo,
    const float* __restrict__ W_in, const float* __restrict__ Wv,
    const float* __restrict__ bv, const float* __restrict__ b_in,
    const float* __restrict__ b_mo, const float* __restrict__ bo)
{
    extern __shared__ float sm[];          // sW[16384] | sV[16384]
    float* sW = sm;
    float* sV = sm + 16384;
    __shared__ float sWo[4][HID], sWiv[4][HID];

    const int b = blockIdx.x, t = threadIdx.x;
    const int r0 = b * 4;

    if (b == 0 && t == 0) g_tile_ctr = 0;  // reset dynamic scheduler each run

    // stage everything with cp.async (no register pressure, deep MLP)
    const uint32_t sWa  = smem_u32(sW);
    const uint32_t sVa  = smem_u32(sV);
    const uint32_t sWoA = smem_u32(&sWo[0][0]);
    const uint32_t sWiA = smem_u32(&sWiv[0][0]);
    // 4 rows x 128 floats = 2048 bytes each = 128 x 16B  (BUG FIX vs R7: was t<32)
    if (t < 128) {
        CPA16(sWoA + t * 16, Wo + r0 * HID + t * 4);
    } else {
        const int i = t - 128;
        CPA16(sWiA + i * 16, W_in + (256 + r0) * HID + i * 4);
    }
    #pragma unroll
    for (int q = 0; q < 16; ++q) {
        const int i = q * 256 + t;
        CPA16(sWa + i * 16, W_mo + i * 4);
        CPA16(sVa + i * 16, Wv + i * 4);
    }
    CPA_WAIT_ALL();
    __syncthreads();

    if (t < HID) {
        float a0 = 0.f, a1 = 0.f, a2 = 0.f, a3 = 0.f;
        #pragma unroll
        for (int j = 0; j < HID; ++j) {
            const float m = sW[j * HID + t];
            a0 += sWo[0][j] * m; a1 += sWo[1][j] * m;
            a2 += sWo[2][j] * m; a3 += sWo[3][j] * m;
        }
        g_A[(r0 + 0) * HID + t] = a0;
        g_A[(r0 + 1) * HID + t] = a1;
        g_A[(r0 + 2) * HID + t] = a2;
        g_A[(r0 + 3) * HID + t] = a3;
    } else {
        const int c = t - HID;
        float a0 = 0.f, a1 = 0.f, a2 = 0.f, a3 = 0.f;
        #pragma unroll
        for (int j = 0; j < HID; ++j) {
            const float m = sV[j * HID + c];
            a0 += sWiv[0][j] * m; a1 += sWiv[1][j] * m;
            a2 += sWiv[2][j] * m; a3 += sWiv[3][j] * m;
        }
        g_B[(r0 + 0) * HID + c] = a0;
        g_B[(r0 + 1) * HID + c] = a1;
        g_B[(r0 + 2) * HID + c] = a2;
        g_B[(r0 + 3) * HID + c] = a3;
    }

    const int wid = t >> 5, lane = t & 31;
    if (wid < 4) {
        float p = 0.f;
        #pragma unroll
        for (int j = lane; j < HID; j += 32) p += sWiv[wid][j] * bv[j];
        p = warp_red(p);
        if (lane == 0) g_u[r0 + wid] = p + b_in[256 + r0 + wid];
    } else {
        const int rr = wid - 4;
        float p = 0.f;
        #pragma unroll
        for (int j = lane; j < HID; j += 32) p += sWo[rr][j] * b_mo[j];
        p = warp_red(p);
        if (lane == 0) g_w[r0 + rr] = p + bo[r0 + rr];
    }
}

// ================= prep2: Bf = bf16(0.5*A@B) fragment layout; c ===========
__global__ __launch_bounds__(256) void prep2()
{
    extern __shared__ float sm[];          // sB[16384]
    float* sB = sm;
    __shared__ float sA[4][HID];

    const int b = blockIdx.x, t = threadIdx.x;
    const int r0 = b * 4;

    const uint32_t sBa = smem_u32(sB);
    const uint32_t sAa = smem_u32(&sA[0][0]);
    // 4 rows x 128 floats = 128 x 16B  (BUG FIX vs R7: was t<32)
    if (t < 128)
        CPA16(sAa + t * 16, g_A + r0 * HID + t * 4);
    #pragma unroll
    for (int q = 0; q < 16; ++q) {
        const int i = q * 256 + t;
        CPA16(sBa + i * 16, g_B + i * 4);
    }
    CPA_WAIT_ALL();
    __syncthreads();

    if (t < HID) {
        float a0 = 0.f, a1 = 0.f, a2 = 0.f, a3 = 0.f;
        #pragma unroll
        for (int j = 0; j < HID; ++j) {
            const float m = sB[j * HID + t];
            a0 += sA[0][j] * m; a1 += sA[1][j] * m;
            a2 += sA[2][j] * m; a3 += sA[3][j] * m;
        }
        float mv[4] = { 0.5f * a0, 0.5f * a1, 0.5f * a2, 0.5f * a3 };
        const int i = t;
        const int ks = i >> 4;
        const int r  = i & 15;
        const int regi = (r >> 3) & 1;
        const int half = r & 1;
        #pragma unroll
        for (int rr = 0; rr < 4; ++rr) {
            const int o = r0 + rr;
            const int nt = o >> 3;
            const int lane2 = ((o & 7) << 2) | ((r & 7) >> 1);
            const int idx = ((((nt * 8 + ks) * 2 + regi) * 32) + lane2) * 2 + half;
            g_Bf[idx] = __float2bfloat16(mv[rr]);
        }
    }

    const int wid = t >> 5, lane = t & 31;
    if (wid < 4) {
        const int o = r0 + wid;
        float p = 0.f;
        #pragma unroll
        for (int j = lane; j < HID; j += 32) p += sA[wid][j] * g_u[j];
        p = warp_red(p);
        if (lane == 0) g_c[o] = 0.5f * (p + g_w[o]);
    }
}

// ================= main =====================================================
// smem: XS0 @0 (64KB fp32 SW128), XS1 @65536, XB0 @131072 (32KB bf16),
//       XB1 @163840, mbar full0/full1 @196608
#define OFF_XS0  0u
#define OFF_XS1  65536u
#define OFF_XB0  131072u
#define OFF_XB1  163840u
#define OFF_MBAR 196608u
#define SMEM_TOTAL 196736

#define MBAR_INIT(a, c) \
    asm volatile("mbarrier.init.shared.b64 [%0], %1;" :: "r"(a), "r"(c) : "memory")
#define MBAR_EXPECT(a, b) \
    asm volatile("mbarrier.arrive.expect_tx.shared.b64 _, [%0], %1;" :: "r"(a), "r"(b) : "memory")
#define MBAR_WAIT(mbar, par) do {                                             \
    uint32_t _m = (mbar); uint32_t _p = (par); uint32_t _d;                   \
    asm volatile("{\n\t.reg .pred p;\n\t"                                     \
        "mbarrier.try_wait.parity.acquire.cta.shared::cta.b64 p, [%1], %2;\n\t" \
        "selp.b32 %0, 1, 0, p;\n\t}"                                          \
        : "=r"(_d) : "r"(_m), "r"(_p) : "memory");                            \
    if (!_d) {                                                                \
        asm volatile("{\n\t.reg .pred P1;\n\t"                                \
            "W_%=:\n\t"                                                       \
            "mbarrier.try_wait.parity.acquire.cta.shared::cta.b64 P1, [%0], %1, 0x989680;\n\t" \
            "@P1 bra.uni D_%=;\n\t"                                           \
            "bra.uni W_%=;\n\t"                                               \
            "D_%=:\n\t}" :: "r"(_m), "r"(_p) : "memory");                     \
    }                                                                         \
} while (0)

#define TMA_LOAD2D(dst, map, x, y, mb) \
    asm volatile("cp.async.bulk.tensor.2d.shared::cta.global.tile.mbarrier::complete_tx::bytes " \
                 "[%0], [%1, {%2, %3}], [%4];" \
                 :: "r"(dst), "l"(map), "r"(x), "r"(y), "r"(mb) : "memory")
#define TMA_STORE2D(map, x, y, src) \
    asm volatile("cp.async.bulk.tensor.2d.global.shared::cta.tile.bulk_group " \
                 "[%0, {%1, %2}], [%3];" \
                 :: "l"(map), "r"(x), "r"(y), "r"(src) : "memory")
#define FENCE_ASYNC() asm volatile("fence.proxy.async.shared::cta;" ::: "memory")

__device__ __forceinline__ uint32_t packbf(float lo, float hi) {
    uint32_t d;
    asm("cvt.rn.bf16x2.f32 %0, %1, %2;" : "=r"(d) : "f"(hi), "f"(lo));
    return d;
}

__global__ __launch_bounds__(NTHREADS, 1) void fused_main(
    const __grid_constant__ CUtensorMap tmX,
    const __grid_constant__ CUtensorMap tmY,
    int ntiles)
{
    extern __shared__ __align__(1024) unsigned char smem_raw[];
    __shared__ unsigned int sCur;
    const uint32_t sb = smem_u32(smem_raw);
    const int tid  = threadIdx.x;
    const int lane = tid & 31, wid = tid >> 5;
    const int wm = wid & 1, wn = wid >> 1;      // 2(m) x 4(n) warp grid
    const uint32_t mb_full[2] = { sb + OFF_MBAR, sb + OFF_MBAR + 8 };
    const uint32_t xs_a[2] = { sb + OFF_XS0, sb + OFF_XS1 };
    const uint32_t xb_a[2] = { sb + OFF_XB0, sb + OFF_XB1 };

    // ---- B fragments into registers (constant across tiles) ----
    uint32_t breg[4][8][2];
    {
        const uint32_t* bp = reinterpret_cast<const uint32_t*>(g_Bf);
        #pragma unroll
        for (int nt = 0; nt < 4; ++nt)
            #pragma unroll
            for (int ks = 0; ks < 8; ++ks)
                #pragma unroll
                for (int ri = 0; ri < 2; ++ri)
                    breg[nt][ks][ri] =
                        bp[(((wn * 4 + nt) * 8 + ks) * 2 + ri) * 32 + lane];
    }
    // ---- c bias (per-thread cols) ----
    float cv[4][2];
    #pragma unroll
    for (int nt = 0; nt < 4; ++nt) {
        const int col = wn * 32 + nt * 8 + 2 * (lane & 3);
        cv[nt][0] = g_c[col];
        cv[nt][1] = g_c[col + 1];
    }

    if (tid == 0) { MBAR_INIT(mb_full[0], 1); MBAR_INIT(mb_full[1], 1); }
    __syncthreads();

    // per-thread constants for the convert pass
    const int crow = tid >> 1, ch = tid & 1;
    const uint32_t cr7 = (uint32_t)(crow & 7);
    // ldmatrix constants
    const int rsub = lane & 15;
    const uint32_t lr7 = (uint32_t)(rsub & 7);
    const int khalf = lane >> 4;
    // epilogue constants
    const uint32_t er7a = (uint32_t)(lane >> 2);
    const uint32_t einner = (uint32_t)(lane & 1) * 8;
    const uint32_t eq16b = (uint32_t)((lane & 3) >> 1);

    // convert helper: fp32 XS[stg] -> bf16 XB[stg]
    auto convert = [&](int stg) {
        const uint32_t rxs = xs_a[stg] + (uint32_t)crow * 128;
        const uint32_t rxb = xb_a[stg] + (uint32_t)crow * 256;
        #pragma unroll
        for (int j = 0; j < 8; ++j) {
            const int cj = ch * 8 + j;
            const uint32_t c32 = (uint32_t)(cj >> 2) * 16384;
            const uint32_t q0 = (uint32_t)((cj & 3) * 2);
            const uint32_t a0 = rxs + c32 + ((q0 ^ cr7) << 4);
            const uint32_t a1 = rxs + c32 + (((q0 + 1) ^ cr7) << 4);
            float x0, x1, x2, x3, y0, y1, y2, y3;
            asm volatile("ld.shared.v4.f32 {%0,%1,%2,%3}, [%4];"
                         : "=f"(x0), "=f"(x1), "=f"(x2), "=f"(x3) : "r"(a0));
            asm volatile("ld.shared.v4.f32 {%0,%1,%2,%3}, [%4];"
                         : "=f"(y0), "=f"(y1), "=f"(y2), "=f"(y3) : "r"(a1));
            const uint32_t p0 = packbf(x0, x1), p1 = packbf(x2, x3);
            const uint32_t p2 = packbf(y0, y1), p3 = packbf(y2, y3);
            const uint32_t ab = rxb + (((uint32_t)cj ^ cr7) << 4);
            asm volatile("st.shared.v4.b32 [%0], {%1,%2,%3,%4};"
                         :: "r"(ab), "r"(p0), "r"(p1), "r"(p2), "r"(p3) : "memory");
        }
    };

    // ---- prologue: two tickets, two loads, convert tile0 ----
    if (tid == 0) {
        const unsigned c0 = atomicAdd(&g_tile_ctr, 1u);
        unsigned c1 = 0xffffffffu;
        if (c0 < (unsigned)ntiles) {
            MBAR_EXPECT(mb_full[0], TILE_BYTES);
            #pragma unroll
            for (int ac = 0; ac < 4; ++ac)
                TMA_LOAD2D(xs_a[0] + ac * 16384, &tmX, ac * 32, (int)c0 * BM, mb_full[0]);
            c1 = atomicAdd(&g_tile_ctr, 1u);
            if (c1 < (unsigned)ntiles) {
                MBAR_EXPECT(mb_full[1], TILE_BYTES);
                #pragma unroll
                for (int ac = 0; ac < 4; ++ac)
                    TMA_LOAD2D(xs_a[1] + ac * 16384, &tmX, ac * 32, (int)c1 * BM, mb_full[1]);
            }
        }
        sCur = c0;
        reinterpret_cast<unsigned*>(smem_raw + OFF_MBAR + 16)[0] = c1;
    }
    __syncthreads();
    int cur = (int)sCur;
    int nxt = (int)reinterpret_cast<unsigned*>(smem_raw + OFF_MBAR + 16)[0];
    if (cur >= ntiles) return;

    unsigned ph = 0;
    MBAR_WAIT(mb_full[0], 0);
    ph ^= 1u;
    convert(0);
    __syncthreads();

    int s = 0;
    while (cur < ntiles) {
        // (a) convert next tile (overlaps the mma below across warps)
        if (nxt < ntiles) {
            MBAR_WAIT(mb_full[s ^ 1], (ph >> (s ^ 1)) & 1);
            ph ^= (1u << (s ^ 1));
            convert(s ^ 1);
        }

        // (b) mma from XB[s]
        const uint32_t xb = xb_a[s];
        float acc[4][4][4];
        #pragma unroll
        for (int mt = 0; mt < 4; ++mt)
            #pragma unroll
            for (int nt = 0; nt < 4; ++nt)
                #pragma unroll
                for (int q = 0; q < 4; ++q) acc[mt][nt][q] = 0.f;

        #pragma unroll
        for (int ks = 0; ks < 8; ++ks) {
            uint32_t a[4][4];
            const uint32_t chunk = (uint32_t)(2 * ks + khalf);
            const uint32_t csw = (chunk ^ lr7) << 4;
            #pragma unroll
            for (int mt = 0; mt < 4; ++mt) {
                const uint32_t addr =
                    xb + (uint32_t)(wm * 64 + mt * 16 + rsub) * 256 + csw;
                asm volatile("ldmatrix.sync.aligned.m8n8.x4.shared.b16 {%0,%1,%2,%3}, [%4];"
                             : "=r"(a[mt][0]), "=r"(a[mt][1]), "=r"(a[mt][2]), "=r"(a[mt][3])
                             : "r"(addr));
            }
            #pragma unroll
            for (int mt = 0; mt < 4; ++mt)
                #pragma unroll
                for (int nt = 0; nt < 4; ++nt) {
                    asm volatile(
                        "mma.sync.aligned.m16n8k16.row.col.f32.bf16.bf16.f32 "
                        "{%0,%1,%2,%3}, {%4,%5,%6,%7}, {%8,%9}, {%0,%1,%2,%3};"
                        : "+f"(acc[mt][nt][0]), "+f"(acc[mt][nt][1]),
                          "+f"(acc[mt][nt][2]), "+f"(acc[mt][nt][3])
                        : "r"(a[mt][0]), "r"(a[mt][1]), "r"(a[mt][2]), "r"(a[mt][3]),
                          "r"(breg[nt][ks][0]), "r"(breg[nt][ks][1]));
                }
        }

        // (c) epilogue: Y = X + acc + c, in place in XS[s]
        {
            const uint32_t xsn = xs_a[s] + (uint32_t)wn * 16384;
            #pragma unroll
            for (int mt = 0; mt < 4; ++mt) {
                const uint32_t rA = (uint32_t)(wm * 64 + mt * 16) + (uint32_t)(lane >> 2);
                const uint32_t rB = rA + 8;
                const uint32_t baseA = xsn + rA * 128;
                const uint32_t baseB = xsn + rB * 128;
                #pragma unroll
                for (int nt = 0; nt < 4; ++nt) {
                    const uint32_t q16 = (uint32_t)(nt * 2) + eq16b;
                    const uint32_t aA = baseA + ((q16 ^ er7a) << 4) + einner;
                    const uint32_t aB = baseB + ((q16 ^ er7a) << 4) + einner;
                    float f0, f1;
                    asm volatile("ld.shared.v2.f32 {%0,%1}, [%2];"
                                 : "=f"(f0), "=f"(f1) : "r"(aA));
                    f0 += acc[mt][nt][0] + cv[nt][0];
                    f1 += acc[mt][nt][1] + cv[nt][1];
                    asm volatile("st.shared.v2.f32 [%0], {%1,%2};"
                                 :: "r"(aA), "f"(f0), "f"(f1) : "memory");
                    asm volatile("ld.shared.v2.f32 {%0,%1}, [%2];"
                                 : "=f"(f0), "=f"(f1) : "r"(aB));
                    f0 += acc[mt][nt][2] + cv[nt][0];
                    f1 += acc[mt][nt][3] + cv[nt][1];
                    asm volatile("st.shared.v2.f32 [%0], {%1,%2};"
                                 :: "r"(aB), "f"(f0), "f"(f1) : "memory");
                }
            }
        }
        FENCE_ASYNC();
        __syncthreads();   // epilogue done; convert(s^1) done

        // (e) store cur, fetch ticket t+2, reload XS[s]
        if (tid == 0) {
            #pragma unroll
            for (int ac = 0; ac < 4; ++ac)
                TMA_STORE2D(&tmY, ac * 32, cur * BM, xs_a[s] + ac * 16384);
            asm volatile("cp.async.bulk.commit_group;" ::: "memory");
            unsigned nn = 0xffffffffu;
            if (nxt < ntiles) {
                nn = atomicAdd(&g_tile_ctr, 1u);
                if (nn < (unsigned)ntiles) {
                    asm volatile("cp.async.bulk.wait_group.read 0;" ::: "memory");
                    MBAR_EXPECT(mb_full[s], TILE_BYTES);
                    #pragma unroll
                    for (int ac = 0; ac < 4; ++ac)
                        TMA_LOAD2D(xs_a[s] + ac * 16384, &tmX, ac * 32, (int)nn * BM, mb_full[s]);
                }
            }
            sCur = nn;
        }
        __syncthreads();
        cur = nxt;
        nxt = (int)sCur;
        s ^= 1;
    }

    if (tid == 0)
        asm volatile("cp.async.bulk.wait_group 0;" ::: "memory");
}

// ================= host ====================================================
typedef CUresult (*PFN_encodeTiled)(
    CUtensorMap*, CUtensorMapDataType, cuuint32_t, void*,
    const cuuint64_t*, const cuuint64_t*, const cuuint32_t*, const cuuint32_t*,
    CUtensorMapInterleave, CUtensorMapSwizzle, CUtensorMapL2promotion,
    CUtensorMapFloatOOBfill);

extern "C" void kernel_launch(void* const* d_in, const int* in_sizes, int n_in,
                              void* d_out, int out_size)
{
    const float* X    = (const float*)d_in[0];
    const float* Wv   = (const float*)d_in[7];
    const float* bv   = (const float*)d_in[8];
    const float* W_in = (const float*)d_in[9];
    const float* b_in = (const float*)d_in[10];
    const float* W_mo = (const float*)d_in[11];
    const float* b_mo = (const float*)d_in[12];
    const float* Wo   = (const float*)d_in[13];
    const float* bo   = (const float*)d_in[14];
    float* Y = (float*)d_out;

    const int E = in_sizes[0] / HID;
    const int ntiles = (E + BM - 1) / BM;

    cudaFuncSetAttribute(prep1, cudaFuncAttributeMaxDynamicSharedMemorySize, 131072);
    cudaFuncSetAttribute(prep2, cudaFuncAttributeMaxDynamicSharedMemorySize, 65536);
    prep1<<<32, 256, 131072>>>(Wo, W_mo, W_in, Wv, bv, b_in, b_mo, bo);
    prep2<<<32, 256, 65536>>>();

    void* pfn = nullptr;
    cudaDriverEntryPointQueryResult qr;
    cudaGetDriverEntryPoint("cuTensorMapEncodeTiled", &pfn, cudaEnableDefault, &qr);
    PFN_encodeTiled encode = (PFN_encodeTiled)pfn;

    CUtensorMap tmX, tmY;
    cuuint64_t dims[2] = { (cuuint64_t)HID, (cuuint64_t)E };
    cuuint64_t str[1]  = { (cuuint64_t)HID * 4 };
    cuuint32_t box[2]  = { 32, 128 };
    cuuint32_t es[2]   = { 1, 1 };
    encode(&tmX, CU_TENSOR_MAP_DATA_TYPE_FLOAT32, 2, (void*)X,
           dims, str, box, es, CU_TENSOR_MAP_INTERLEAVE_NONE,
           CU_TENSOR_MAP_SWIZZLE_128B, CU_TENSOR_MAP_L2_PROMOTION_L2_128B,
           CU_TENSOR_MAP_FLOAT_OOB_FILL_NONE);
    encode(&tmY, CU_TENSOR_MAP_DATA_TYPE_FLOAT32, 2, (void*)Y,
           dims, str, box, es, CU_TENSOR_MAP_INTERLEAVE_NONE,
           CU_TENSOR_MAP_SWIZZLE_128B, CU_TENSOR_MAP_L2_PROMOTION_L2_128B,
           CU_TENSOR_MAP_FLOAT_OOB_FILL_NONE);

    cudaFuncSetAttribute(fused_main, cudaFuncAttributeMaxDynamicSharedMemorySize, SMEM_TOTAL);
    fused_main<<<GRID, NTHREADS, SMEM_TOTAL>>>(tmX, tmY, ntiles);
}

// round 9
// speedup vs baseline: 1.4071x; 1.4071x over previous
#include <cuda_runtime.h>
#include <cuda.h>
#include <cuda_bf16.h>
#include <cstdint>
#include <cstddef>

#define HID 128
#define BM 128
#define TILE_BYTES 65536
#define GRID 148
#define NTHREADS 256

// ---------------- device scratch ----------------
__device__ float g_A[HID * HID];                 // Wo @ W_mo
__device__ float g_B[HID * HID];                 // Wiv @ Wv
__device__ float g_u[HID];
__device__ float g_w[HID];
__device__ __nv_bfloat16 g_Bf[16 * 8 * 2 * 32 * 2]; // 0.5*M^T bf16, mma-B-fragment layout
__device__ float g_c[HID];                       // 0.5*(A@u + w)
__device__ unsigned int g_tile_ctr;              // dynamic tile tickets (reset in prep1)

__device__ __forceinline__ uint32_t smem_u32(const void* p) {
    uint32_t a;
    asm("{ .reg .u64 t; cvta.to.shared.u64 t, %1; cvt.u32.u64 %0, t; }" : "=r"(a) : "l"(p));
    return a;
}
__device__ __forceinline__ float warp_red(float p) {
    p += __shfl_xor_sync(0xffffffffu, p, 16);
    p += __shfl_xor_sync(0xffffffffu, p, 8);
    p += __shfl_xor_sync(0xffffffffu, p, 4);
    p += __shfl_xor_sync(0xffffffffu, p, 2);
    p += __shfl_xor_sync(0xffffffffu, p, 1);
    return p;
}
#define CPA16(dst, src) \
    asm volatile("cp.async.cg.shared.global [%0], [%1], 16;" :: "r"(dst), "l"(src))
#define CPA_WAIT_ALL() \
    asm volatile("cp.async.commit_group;\ncp.async.wait_group 0;" ::: "memory")

// ================= prep1: A = Wo@W_mo, B = Wiv@Wv, u, w ===================
// 64 blocks x 2 rows; full weight matrices staged in one cp.async burst.
__global__ __launch_bounds__(256) void prep1(
    const float* __restrict__ Wo, const float* __restrict__ W_mo,
    const float* __restrict__ W_in, const float* __restrict__ Wv,
    const float* __restrict__ bv, const float* __restrict__ b_in,
    const float* __restrict__ b_mo, const float* __restrict__ bo)
{
    extern __shared__ float sm[];          // sW[16384] | sV[16384]
    float* sW = sm;
    float* sV = sm + 16384;
    __shared__ float sWo[2][HID], sWiv[2][HID];

    const int b = blockIdx.x, t = threadIdx.x;
    const int r0 = b * 2;

    if (b == 0 && t == 0) g_tile_ctr = 0;  // reset dynamic scheduler each run

    const uint32_t sWa  = smem_u32(sW);
    const uint32_t sVa  = smem_u32(sV);
    const uint32_t sWoA = smem_u32(&sWo[0][0]);
    const uint32_t sWiA = smem_u32(&sWiv[0][0]);
    // 2 rows x 128 floats = 1024 B each = 64 x 16B
    if (t < 64) {
        CPA16(sWoA + t * 16, Wo + r0 * HID + t * 4);
    } else if (t < 128) {
        const int i = t - 64;
        CPA16(sWiA + i * 16, W_in + (256 + r0) * HID + i * 4);
    }
    #pragma unroll
    for (int q = 0; q < 16; ++q) {
        const int i = q * 256 + t;
        CPA16(sWa + i * 16, W_mo + i * 4);
        CPA16(sVa + i * 16, Wv + i * 4);
    }
    CPA_WAIT_ALL();
    __syncthreads();

    if (t < HID) {
        float a0 = 0.f, a1 = 0.f;
        #pragma unroll
        for (int j = 0; j < HID; ++j) {
            const float m = sW[j * HID + t];
            a0 += sWo[0][j] * m;
            a1 += sWo[1][j] * m;
        }
        g_A[(r0 + 0) * HID + t] = a0;
        g_A[(r0 + 1) * HID + t] = a1;
    } else {
        const int c = t - HID;
        float a0 = 0.f, a1 = 0.f;
        #pragma unroll
        for (int j = 0; j < HID; ++j) {
            const float m = sV[j * HID + c];
            a0 += sWiv[0][j] * m;
            a1 += sWiv[1][j] * m;
        }
        g_B[(r0 + 0) * HID + c] = a0;
        g_B[(r0 + 1) * HID + c] = a1;
    }

    const int wid = t >> 5, lane = t & 31;
    if (wid < 2) {
        float p = 0.f;
        #pragma unroll
        for (int j = lane; j < HID; j += 32) p += sWiv[wid][j] * bv[j];
        p = warp_red(p);
        if (lane == 0) g_u[r0 + wid] = p + b_in[256 + r0 + wid];
    } else if (wid < 4) {
        const int rr = wid - 2;
        float p = 0.f;
        #pragma unroll
        for (int j = lane; j < HID; j += 32) p += sWo[rr][j] * b_mo[j];
        p = warp_red(p);
        if (lane == 0) g_w[r0 + rr] = p + bo[r0 + rr];
    }
}

// ================= prep2: Bf = bf16(0.5*A@B) fragment layout; c ===========
__global__ __launch_bounds__(256) void prep2()
{
    extern __shared__ float sm[];          // sB[16384]
    float* sB = sm;
    __shared__ float sA[2][HID];

    const int b = blockIdx.x, t = threadIdx.x;
    const int r0 = b * 2;

    const uint32_t sBa = smem_u32(sB);
    const uint32_t sAa = smem_u32(&sA[0][0]);
    if (t < 64)
        CPA16(sAa + t * 16, g_A + r0 * HID + t * 4);
    #pragma unroll
    for (int q = 0; q < 16; ++q) {
        const int i = q * 256 + t;
        CPA16(sBa + i * 16, g_B + i * 4);
    }
    CPA_WAIT_ALL();
    __syncthreads();

    if (t < HID) {
        float a0 = 0.f, a1 = 0.f;
        #pragma unroll
        for (int j = 0; j < HID; ++j) {
            const float m = sB[j * HID + t];
            a0 += sA[0][j] * m;
            a1 += sA[1][j] * m;
        }
        float mv[2] = { 0.5f * a0, 0.5f * a1 };
        const int i = t;
        const int ks = i >> 4;
        const int r  = i & 15;
        const int regi = (r >> 3) & 1;
        const int half = r & 1;
        #pragma unroll
        for (int rr = 0; rr < 2; ++rr) {
            const int o = r0 + rr;
            const int nt = o >> 3;
            const int lane2 = ((o & 7) << 2) | ((r & 7) >> 1);
            const int idx = ((((nt * 8 + ks) * 2 + regi) * 32) + lane2) * 2 + half;
            g_Bf[idx] = __float2bfloat16(mv[rr]);
        }
    }

    const int wid = t >> 5, lane = t & 31;
    if (wid < 2) {
        const int o = r0 + wid;
        float p = 0.f;
        #pragma unroll
        for (int j = lane; j < HID; j += 32) p += sA[wid][j] * g_u[j];
        p = warp_red(p);
        if (lane == 0) g_c[o] = 0.5f * (p + g_w[o]);
    }
}

// ================= main =====================================================
// smem: XS0 @0, XS1 @65536, XS2 @131072 (each 64KB fp32 SW128),
//       XB @196608 (32KB bf16), mbar full0/1/2 @229376, sTick[3] @229400
#define OFF_XS0  0u
#define OFF_XS1  65536u
#define OFF_XS2  131072u
#define OFF_XB   196608u
#define OFF_MBAR 229376u
#define OFF_TICK 229400u
#define SMEM_TOTAL 229440

#define MBAR_INIT(a, c) \
    asm volatile("mbarrier.init.shared.b64 [%0], %1;" :: "r"(a), "r"(c) : "memory")
#define MBAR_EXPECT(a, b) \
    asm volatile("mbarrier.arrive.expect_tx.shared.b64 _, [%0], %1;" :: "r"(a), "r"(b) : "memory")
#define MBAR_WAIT(mbar, par) do {                                             \
    uint32_t _m = (mbar); uint32_t _p = (par); uint32_t _d;                   \
    asm volatile("{\n\t.reg .pred p;\n\t"                                     \
        "mbarrier.try_wait.parity.acquire.cta.shared::cta.b64 p, [%1], %2;\n\t" \
        "selp.b32 %0, 1, 0, p;\n\t}"                                          \
        : "=r"(_d) : "r"(_m), "r"(_p) : "memory");                            \
    if (!_d) {                                                                \
        asm volatile("{\n\t.reg .pred P1;\n\t"                                \
            "W_%=:\n\t"                                                       \
            "mbarrier.try_wait.parity.acquire.cta.shared::cta.b64 P1, [%0], %1, 0x989680;\n\t" \
            "@P1 bra.uni D_%=;\n\t"                                           \
            "bra.uni W_%=;\n\t"                                               \
            "D_%=:\n\t}" :: "r"(_m), "r"(_p) : "memory");                     \
    }                                                                         \
} while (0)

#define TMA_LOAD2D(dst, map, x, y, mb) \
    asm volatile("cp.async.bulk.tensor.2d.shared::cta.global.tile.mbarrier::complete_tx::bytes " \
                 "[%0], [%1, {%2, %3}], [%4];" \
                 :: "r"(dst), "l"(map), "r"(x), "r"(y), "r"(mb) : "memory")
#define TMA_STORE2D(map, x, y, src) \
    asm volatile("cp.async.bulk.tensor.2d.global.shared::cta.tile.bulk_group " \
                 "[%0, {%1, %2}], [%3];" \
                 :: "l"(map), "r"(x), "r"(y), "r"(src) : "memory")
#define FENCE_ASYNC() asm volatile("fence.proxy.async.shared::cta;" ::: "memory")

__device__ __forceinline__ uint32_t packbf(float lo, float hi) {
    uint32_t d;
    asm("cvt.rn.bf16x2.f32 %0, %1, %2;" : "=r"(d) : "f"(hi), "f"(lo));
    return d;
}

__global__ __launch_bounds__(NTHREADS, 1) void fused_main(
    const __grid_constant__ CUtensorMap tmX,
    const __grid_constant__ CUtensorMap tmY,
    int ntiles)
{
    extern __shared__ __align__(1024) unsigned char smem_raw[];
    const uint32_t sb = smem_u32(smem_raw);
    const int tid  = threadIdx.x;
    const int lane = tid & 31, wid = tid >> 5;
    const int wm = wid & 1, wn = wid >> 1;      // 2(m) x 4(n) warp grid
    const uint32_t mb_full[3] = { sb + OFF_MBAR, sb + OFF_MBAR + 8, sb + OFF_MBAR + 16 };
    const uint32_t xs_a[3] = { sb + OFF_XS0, sb + OFF_XS1, sb + OFF_XS2 };
    const uint32_t xb = sb + OFF_XB;
    unsigned* sTick = reinterpret_cast<unsigned*>(smem_raw + (OFF_TICK));

    // ---- B fragments into registers (constant across tiles) ----
    uint32_t breg[4][8][2];
    {
        const uint32_t* bp = reinterpret_cast<const uint32_t*>(g_Bf);
        #pragma unroll
        for (int nt = 0; nt < 4; ++nt)
            #pragma unroll
            for (int ks = 0; ks < 8; ++ks)
                #pragma unroll
                for (int ri = 0; ri < 2; ++ri)
                    breg[nt][ks][ri] =
                        bp[(((wn * 4 + nt) * 8 + ks) * 2 + ri) * 32 + lane];
    }
    // ---- c bias (per-thread cols) ----
    float cv[4][2];
    #pragma unroll
    for (int nt = 0; nt < 4; ++nt) {
        const int col = wn * 32 + nt * 8 + 2 * (lane & 3);
        cv[nt][0] = g_c[col];
        cv[nt][1] = g_c[col + 1];
    }

    if (tid == 0) {
        MBAR_INIT(mb_full[0], 1);
        MBAR_INIT(mb_full[1], 1);
        MBAR_INIT(mb_full[2], 1);
    }
    __syncthreads();

    // ---- prologue: 3 tickets, 3 loads ----
    if (tid == 0) {
        #pragma unroll
        for (int st = 0; st < 3; ++st) {
            const unsigned c = atomicAdd(&g_tile_ctr, 1u);
            sTick[st] = c;
            if (c < (unsigned)ntiles) {
                MBAR_EXPECT(mb_full[st], TILE_BYTES);
                #pragma unroll
                for (int ac = 0; ac < 4; ++ac)
                    TMA_LOAD2D(xs_a[st] + ac * 16384, &tmX, ac * 32, (int)c * BM, mb_full[st]);
            }
        }
    }
    __syncthreads();

    // per-thread constants for the convert pass
    const int crow = tid >> 1, ch = tid & 1;
    const uint32_t cr7 = (uint32_t)(crow & 7);
    // ldmatrix constants
    const int rsub = lane & 15;
    const uint32_t lr7 = (uint32_t)(rsub & 7);
    const int khalf = lane >> 4;
    // epilogue constants
    const uint32_t er7a = (uint32_t)(lane >> 2);
    const uint32_t einner = (uint32_t)(lane & 1) * 8;
    const uint32_t eq16b = (uint32_t)((lane & 3) >> 1);

    unsigned ph = 0;
    int pend_stage = -1;
    unsigned pend_tick = 0;

    for (int i = 0; ; ++i) {
        const int p = i % 3;
        const unsigned q = sTick[p];
        if (q >= (unsigned)ntiles) break;

        // wait X tile for stage p
        MBAR_WAIT(mb_full[p], (ph >> p) & 1);
        ph ^= (1u << p);

        // ---- convert fp32 XS[p] -> bf16 XB (swizzled 256B rows) ----
        {
            const uint32_t rxs = xs_a[p] + (uint32_t)crow * 128;
            const uint32_t rxb = xb + (uint32_t)crow * 256;
            #pragma unroll
            for (int j = 0; j < 8; ++j) {
                const int cj = ch * 8 + j;
                const uint32_t c32 = (uint32_t)(cj >> 2) * 16384;
                const uint32_t q0 = (uint32_t)((cj & 3) * 2);
                const uint32_t a0 = rxs + c32 + ((q0 ^ cr7) << 4);
                const uint32_t a1 = rxs + c32 + (((q0 + 1) ^ cr7) << 4);
                float x0, x1, x2, x3, y0, y1, y2, y3;
                asm volatile("ld.shared.v4.f32 {%0,%1,%2,%3}, [%4];"
                             : "=f"(x0), "=f"(x1), "=f"(x2), "=f"(x3) : "r"(a0));
                asm volatile("ld.shared.v4.f32 {%0,%1,%2,%3}, [%4];"
                             : "=f"(y0), "=f"(y1), "=f"(y2), "=f"(y3) : "r"(a1));
                const uint32_t p0 = packbf(x0, x1), p1 = packbf(x2, x3);
                const uint32_t p2 = packbf(y0, y1), p3 = packbf(y2, y3);
                const uint32_t ab = rxb + (((uint32_t)cj ^ cr7) << 4);
                asm volatile("st.shared.v4.b32 [%0], {%1,%2,%3,%4};"
                             :: "r"(ab), "r"(p0), "r"(p1), "r"(p2), "r"(p3) : "memory");
            }
        }
        __syncthreads();   // XB ready

        // ---- mma from XB ----
        float acc[4][4][4];
        #pragma unroll
        for (int mt = 0; mt < 4; ++mt)
            #pragma unroll
            for (int nt = 0; nt < 4; ++nt)
                #pragma unroll
                for (int qq = 0; qq < 4; ++qq) acc[mt][nt][qq] = 0.f;

        #pragma unroll
        for (int ks = 0; ks < 8; ++ks) {
            uint32_t a[4][4];
            const uint32_t chunk = (uint32_t)(2 * ks + khalf);
            const uint32_t csw = (chunk ^ lr7) << 4;
            #pragma unroll
            for (int mt = 0; mt < 4; ++mt) {
                const uint32_t addr =
                    xb + (uint32_t)(wm * 64 + mt * 16 + rsub) * 256 + csw;
                asm volatile("ldmatrix.sync.aligned.m8n8.x4.shared.b16 {%0,%1,%2,%3}, [%4];"
                             : "=r"(a[mt][0]), "=r"(a[mt][1]), "=r"(a[mt][2]), "=r"(a[mt][3])
                             : "r"(addr));
            }
            #pragma unroll
            for (int mt = 0; mt < 4; ++mt)
                #pragma unroll
                for (int nt = 0; nt < 4; ++nt) {
                    asm volatile(
                        "mma.sync.aligned.m16n8k16.row.col.f32.bf16.bf16.f32 "
                        "{%0,%1,%2,%3}, {%4,%5,%6,%7}, {%8,%9}, {%0,%1,%2,%3};"
                        : "+f"(acc[mt][nt][0]), "+f"(acc[mt][nt][1]),
                          "+f"(acc[mt][nt][2]), "+f"(acc[mt][nt][3])
                        : "r"(a[mt][0]), "r"(a[mt][1]), "r"(a[mt][2]), "r"(a[mt][3]),
                          "r"(breg[nt][ks][0]), "r"(breg[nt][ks][1]));
                }
        }

        // ---- epilogue: Y = X + acc + c, in place in XS[p] ----
        {
            const uint32_t xsn = xs_a[p] + (uint32_t)wn * 16384;
            #pragma unroll
            for (int mt = 0; mt < 4; ++mt) {
                const uint32_t rA = (uint32_t)(wm * 64 + mt * 16) + (uint32_t)(lane >> 2);
                const uint32_t rB = rA + 8;
                const uint32_t baseA = xsn + rA * 128;
                const uint32_t baseB = xsn + rB * 128;
                #pragma unroll
                for (int nt = 0; nt < 4; ++nt) {
                    const uint32_t q16 = (uint32_t)(nt * 2) + eq16b;
                    const uint32_t aA = baseA + ((q16 ^ er7a) << 4) + einner;
                    const uint32_t aB = baseB + ((q16 ^ er7a) << 4) + einner;
                    float f0, f1;
                    asm volatile("ld.shared.v2.f32 {%0,%1}, [%2];"
                                 : "=f"(f0), "=f"(f1) : "r"(aA));
                    f0 += acc[mt][nt][0] + cv[nt][0];
                    f1 += acc[mt][nt][1] + cv[nt][1];
                    asm volatile("st.shared.v2.f32 [%0], {%1,%2};"
                                 :: "r"(aA), "f"(f0), "f"(f1) : "memory");
                    asm volatile("ld.shared.v2.f32 {%0,%1}, [%2];"
                                 : "=f"(f0), "=f"(f1) : "r"(aB));
                    f0 += acc[mt][nt][2] + cv[nt][0];
                    f1 += acc[mt][nt][3] + cv[nt][1];
                    asm volatile("st.shared.v2.f32 [%0], {%1,%2};"
                                 :: "r"(aB), "f"(f0), "f"(f1) : "memory");
                }
            }
        }
        FENCE_ASYNC();
        __syncthreads();   // epilogue done in XS[p]

        // ---- tid0: deferred reload (stage stored last iter), store cur, new ticket ----
        if (tid == 0) {
            if (pend_stage >= 0) {
                // store of XS[pend_stage] was committed one iteration ago -> read done
                asm volatile("cp.async.bulk.wait_group.read 0;" ::: "memory");
                if (pend_tick < (unsigned)ntiles) {
                    MBAR_EXPECT(mb_full[pend_stage], TILE_BYTES);
                    #pragma unroll
                    for (int ac = 0; ac < 4; ++ac)
                        TMA_LOAD2D(xs_a[pend_stage] + ac * 16384, &tmX,
                                   ac * 32, (int)pend_tick * BM, mb_full[pend_stage]);
                }
            }
            #pragma unroll
            for (int ac = 0; ac < 4; ++ac)
                TMA_STORE2D(&tmY, ac * 32, (int)q * BM, xs_a[p] + ac * 16384);
            asm volatile("cp.async.bulk.commit_group;" ::: "memory");
            const unsigned nn = atomicAdd(&g_tile_ctr, 1u);
            sTick[p] = nn;        // consumed 3 iterations later (syncs in between)
            pend_stage = p;
            pend_tick = nn;
        }
        // no extra sync: next iteration's convert writes XB, which all warps
        // finished reading before the sync above.
    }

    if (tid == 0)
        asm volatile("cp.async.bulk.wait_group 0;" ::: "memory");
}

// ================= host ====================================================
typedef CUresult (*PFN_encodeTiled)(
    CUtensorMap*, CUtensorMapDataType, cuuint32_t, void*,
    const cuuint64_t*, const cuuint64_t*, const cuuint32_t*, const cuuint32_t*,
    CUtensorMapInterleave, CUtensorMapSwizzle, CUtensorMapL2promotion,
    CUtensorMapFloatOOBfill);

extern "C" void kernel_launch(void* const* d_in, const int* in_sizes, int n_in,
                              void* d_out, int out_size)
{
    const float* X    = (const float*)d_in[0];
    const float* Wv   = (const float*)d_in[7];
    const float* bv   = (const float*)d_in[8];
    const float* W_in = (const float*)d_in[9];
    const float* b_in = (const float*)d_in[10];
    const float* W_mo = (const float*)d_in[11];
    const float* b_mo = (const float*)d_in[12];
    const float* Wo   = (const float*)d_in[13];
    const float* bo   = (const float*)d_in[14];
    float* Y = (float*)d_out;

    const int E = in_sizes[0] / HID;
    const int ntiles = (E + BM - 1) / BM;

    cudaFuncSetAttribute(prep1, cudaFuncAttributeMaxDynamicSharedMemorySize, 131072);
    cudaFuncSetAttribute(prep2, cudaFuncAttributeMaxDynamicSharedMemorySize, 65536);
    prep1<<<64, 256, 131072>>>(Wo, W_mo, W_in, Wv, bv, b_in, b_mo, bo);
    prep2<<<64, 256, 65536>>>();

    void* pfn = nullptr;
    cudaDriverEntryPointQueryResult qr;
    cudaGetDriverEntryPoint("cuTensorMapEncodeTiled", &pfn, cudaEnableDefault, &qr);
    PFN_encodeTiled encode = (PFN_encodeTiled)pfn;

    CUtensorMap tmX, tmY;
    cuuint64_t dims[2] = { (cuuint64_t)HID, (cuuint64_t)E };
    cuuint64_t str[1]  = { (cuuint64_t)HID * 4 };
    cuuint32_t box[2]  = { 32, 128 };
    cuuint32_t es[2]   = { 1, 1 };
    encode(&tmX, CU_TENSOR_MAP_DATA_TYPE_FLOAT32, 2, (void*)X,
           dims, str, box, es, CU_TENSOR_MAP_INTERLEAVE_NONE,
           CU_TENSOR_MAP_SWIZZLE_128B, CU_TENSOR_MAP_L2_PROMOTION_L2_128B,
           CU_TENSOR_MAP_FLOAT_OOB_FILL_NONE);
    encode(&tmY, CU_TENSOR_MAP_DATA_TYPE_FLOAT32, 2, (void*)Y,
           dims, str, box, es, CU_TENSOR_MAP_INTERLEAVE_NONE,
           CU_TENSOR_MAP_SWIZZLE_128B, CU_TENSOR_MAP_L2_PROMOTION_L2_128B,
           CU_TENSOR_MAP_FLOAT_OOB_FILL_NONE);

    cudaFuncSetAttribute(fused_main, cudaFuncAttributeMaxDynamicSharedMemorySize, SMEM_TOTAL);
    fused_main<<<GRID, NTHREADS, SMEM_TOTAL>>>(tmX, tmY, ntiles);
}